// round 14
// baseline (speedup 1.0000x reference)
#include <cuda_runtime.h>
#include <cuda_fp16.h>
#include <cstdint>

#define D_   1024
#define H_   16
#define HD_  64
#define B_   2
#define S_   2048
#define M_   (B_ * S_)          // 4096

// ---------------- scratch (device globals) ---------------------------------
__device__ unsigned g_q16[(size_t)M_ * D_ / 2];     // fp16 natural inputs
__device__ unsigned g_k16[(size_t)M_ * D_ / 2];
__device__ unsigned g_v16[(size_t)M_ * D_ / 2];
__device__ unsigned g_w16[4][(size_t)D_ * D_ / 2];  // Wq,Wk,Wv,Wo fp16
__device__ unsigned g_Qh[(size_t)M_ * D_ / 2];      // [B,H,S,32w] natural, *SC
__device__ unsigned g_Kh[(size_t)M_ * D_ / 2];      // [B,H,S,32w] natural
__device__ unsigned g_Vh[(size_t)M_ * D_ / 2];      // [B,H,64,S] natural (transposed)
__device__ unsigned g_Ch[(size_t)M_ * D_ / 2];      // ctx [M,512w] natural

#define SC_Q 0.18033688011112042f   /* 0.125 * log2(e) */
#define ONES2 0x3C003C00u           /* (1.0h, 1.0h) */

// ---------------------------------------------------------------------------
// helpers
// ---------------------------------------------------------------------------
__device__ __forceinline__ unsigned pack2(float lo, float hi) {
    unsigned r;
    asm("cvt.rn.f16x2.f32 %0, %1, %2;" : "=r"(r) : "f"(hi), "f"(lo));
    return r;
}
__device__ __forceinline__ float ex2(float x) {
    float y; asm("ex2.approx.ftz.f32 %0, %1;" : "=f"(y) : "f"(x)); return y;
}
__device__ __forceinline__ void mma_f16(float c[4], const unsigned a[4], unsigned b0, unsigned b1) {
    asm volatile(
        "mma.sync.aligned.m16n8k16.row.col.f32.f16.f16.f32 "
        "{%0,%1,%2,%3}, {%4,%5,%6,%7}, {%8,%9}, {%0,%1,%2,%3};\n"
        : "+f"(c[0]), "+f"(c[1]), "+f"(c[2]), "+f"(c[3])
        : "r"(a[0]), "r"(a[1]), "r"(a[2]), "r"(a[3]), "r"(b0), "r"(b1));
}
__device__ __forceinline__ void ldsm4(unsigned& r0, unsigned& r1, unsigned& r2, unsigned& r3,
                                      unsigned addr) {
    asm volatile("ldmatrix.sync.aligned.m8n8.x4.shared.b16 {%0,%1,%2,%3}, [%4];"
                 : "=r"(r0), "=r"(r1), "=r"(r2), "=r"(r3) : "r"(addr));
}
#define CP16(dst, src) \
    asm volatile("cp.async.cg.shared.global [%0], [%1], 16;" :: "r"(dst), "l"(src) : "memory")
#define CP_COMMIT() asm volatile("cp.async.commit_group;" ::: "memory")
#define CP_WAIT4()  asm volatile("cp.async.wait_group 4;" ::: "memory")
#define CP_WAIT1()  asm volatile("cp.async.wait_group 1;" ::: "memory")
#define CP_WAIT0()  asm volatile("cp.async.wait_group 0;" ::: "memory")

// ---------------------------------------------------------------------------
// convert: fp32 -> fp16 natural (q,k,v + 4 weights)
// ---------------------------------------------------------------------------
__global__ __launch_bounds__(256) void convert_kernel(
    const float* __restrict__ q, const float* __restrict__ k, const float* __restrict__ v,
    const float* __restrict__ wq, const float* __restrict__ wk,
    const float* __restrict__ wv, const float* __restrict__ wo)
{
    const int z = blockIdx.z;
    const float* src;
    unsigned* dst;
    size_t n;
    switch (z) {
        case 0: src = q;  dst = g_q16;    n = (size_t)M_ * D_; break;
        case 1: src = k;  dst = g_k16;    n = (size_t)M_ * D_; break;
        case 2: src = v;  dst = g_v16;    n = (size_t)M_ * D_; break;
        case 3: src = wq; dst = g_w16[0]; n = (size_t)D_ * D_; break;
        case 4: src = wk; dst = g_w16[1]; n = (size_t)D_ * D_; break;
        case 5: src = wv; dst = g_w16[2]; n = (size_t)D_ * D_; break;
        default: src = wo; dst = g_w16[3]; n = (size_t)D_ * D_; break;
    }
    const size_t i8 = ((size_t)blockIdx.x * blockDim.x + threadIdx.x) * 8;
    if (i8 >= n) return;
    float4 f0 = *(const float4*)(src + i8);
    float4 f1 = *(const float4*)(src + i8 + 4);
    uint4 o = make_uint4(pack2(f0.x, f0.y), pack2(f0.z, f0.w),
                         pack2(f1.x, f1.y), pack2(f1.z, f1.w));
    *(uint4*)(dst + i8 / 2) = o;
}

// ---------------------------------------------------------------------------
// fp16 GEMM: C[m,e] = A[m,:] . W[e,:] + bias[e]
// CTA 256(m) x 128(n), 256 threads (8 warps 4x2, warp tile 64x64 — the
// proven fragment economy), BK=64 halves, 3-stage cp.async, SW128 smem,
// ldmatrix fragments.  Halves B-weight L2 fan-out vs 128x128.
// modes: 0 float out [M,D]; 1 Q natural *SC; 2 K natural; 3 V transposed nat.
// ---------------------------------------------------------------------------
#define GSTG    3
#define SMA_STG 32768     // 256 rows x 128 B
#define SMB_STG 16384     // 128 rows x 128 B
#define GM_SMEM (GSTG * (SMA_STG + SMB_STG))   // 147456

__device__ __forceinline__ void gemm16_body(
    const unsigned* __restrict__ Aw,
    const unsigned* __restrict__ Ww,
    const float* __restrict__ bias,
    void* __restrict__ outp,
    int mode)
{
    extern __shared__ char smc[];
    const unsigned smA = (unsigned)__cvta_generic_to_shared(smc);
    const unsigned smB = smA + GSTG * SMA_STG;

    const int t    = threadIdx.x;
    const int lane = t & 31;
    const int w    = t >> 5;
    const int gp   = lane >> 2;
    const int tg   = lane & 3;
    const int wm0  = (w >> 1) << 6;    // 0,64,128,192
    const int wn0  = (w & 1) << 6;     // 0,64

    const int m0 = blockIdx.y << 8;    // 256-row tile
    const int n0 = blockIdx.x << 7;    // 128-col tile

    const unsigned* Ab = Aw + (size_t)m0 * 512;
    const unsigned* Bb = Ww + (size_t)n0 * 512;

    const int lr = t >> 3;   // 0..31
    const int lc = t & 7;

    const int la15 = lane & 15;
    const int ahi  = (lane >> 4) << 4;
    const int bsel = ((lane >> 3) & 1) << 4;
    const int brow0 = wn0 + ((lane >> 4) << 3) + (lane & 7);

    int arow[4], akey[4];
#pragma unroll
    for (int mi = 0; mi < 4; mi++) {
        const int r = wm0 + 16 * mi + la15;
        arow[mi] = 128 * r;
        akey[mi] = (r & 7) << 4;
    }

    float acc[4][8][4];
#pragma unroll
    for (int mi = 0; mi < 4; mi++)
#pragma unroll
        for (int nj = 0; nj < 8; nj++)
#pragma unroll
            for (int q = 0; q < 4; q++) acc[mi][nj][q] = 0.0f;

#define GISSUE(st, kc) do {                                                    \
    const unsigned da = smA + (st) * SMA_STG;                                  \
    const unsigned db = smB + (st) * SMB_STG;                                  \
    _Pragma("unroll")                                                          \
    for (int i = 0; i < 8; i++) {                                              \
        const int row = lr + 32 * i;                                           \
        const unsigned off = 128u * row + ((16u * lc) ^ ((row & 7) << 4));     \
        CP16(da + off, Ab + (size_t)row * 512 + (kc) * 32 + 4 * lc);           \
    }                                                                          \
    _Pragma("unroll")                                                          \
    for (int i = 0; i < 4; i++) {                                              \
        const int row = lr + 32 * i;                                           \
        const unsigned off = 128u * row + ((16u * lc) ^ ((row & 7) << 4));     \
        CP16(db + off, Bb + (size_t)row * 512 + (kc) * 32 + 4 * lc);           \
    }                                                                          \
    CP_COMMIT();                                                               \
} while (0)

    GISSUE(0, 0);
    GISSUE(1, 1);

    for (int kc = 0; kc < 16; kc++) {
        if (kc == 15) { CP_WAIT0(); } else { CP_WAIT1(); }
        __syncthreads();
        if (kc + 2 < 16) {
            const int st = (kc + 2) % 3;
            GISSUE(st, kc + 2);
        }

        const unsigned ab = smA + (kc % 3) * SMA_STG;
        const unsigned bb = smB + (kc % 3) * SMB_STG;

#pragma unroll
        for (int s = 0; s < 4; s++) {
            unsigned a[4][4];
#pragma unroll
            for (int mi = 0; mi < 4; mi++) {
                const unsigned addr = ab + arow[mi] + ((32 * s + ahi) ^ akey[mi]);
                ldsm4(a[mi][0], a[mi][1], a[mi][2], a[mi][3], addr);
            }
#pragma unroll
            for (int nj2 = 0; nj2 < 4; nj2++) {
                const int row = brow0 + 16 * nj2;
                const unsigned addr = bb + 128u * row + ((32 * s + bsel) ^ ((row & 7) << 4));
                unsigned b0, b1, b2, b3;
                ldsm4(b0, b1, b2, b3, addr);
#pragma unroll
                for (int mi = 0; mi < 4; mi++) {
                    mma_f16(acc[mi][2 * nj2],     a[mi], b0, b1);
                    mma_f16(acc[mi][2 * nj2 + 1], a[mi], b2, b3);
                }
            }
        }
    }
#undef GISSUE

    // ---- epilogue
#pragma unroll
    for (int mi = 0; mi < 4; mi++) {
#pragma unroll
        for (int h = 0; h < 2; h++) {
            const int m  = m0 + wm0 + 16 * mi + gp + 8 * h;
            const int b_ = m >> 11;
            const int s  = m & (S_ - 1);
#pragma unroll
            for (int nj = 0; nj < 8; nj++) {
                const int e  = n0 + wn0 + 8 * nj + 2 * tg;
                const float vx = acc[mi][nj][2 * h]     + bias[e];
                const float vy = acc[mi][nj][2 * h + 1] + bias[e + 1];
                if (mode == 0) {
                    *(float2*)((float*)outp + (size_t)m * D_ + e) = make_float2(vx, vy);
                } else if (mode == 1 || mode == 2) {
                    const int hh = e >> 6, hd = e & 63;
                    const float sc = (mode == 1) ? SC_Q : 1.0f;
                    ((unsigned*)outp)[(((size_t)(b_ * H_ + hh) * S_ + s) << 5) + (hd >> 1)] =
                        pack2(vx * sc, vy * sc);
                } else {
                    // V: natural transposed [b,h,hd][s]
                    const int hh = e >> 6, hd = e & 63;
                    __half* vo = (__half*)outp + (((size_t)(b_ * H_ + hh) * HD_ + hd)) * S_ + s;
                    vo[0]  = __float2half_rn(vx);
                    vo[S_] = __float2half_rn(vy);
                }
            }
        }
    }
}

__global__ __launch_bounds__(256, 1) void qkv_gemm_kernel(
    const float* __restrict__ bq, const float* __restrict__ bk, const float* __restrict__ bv)
{
    const int z = blockIdx.z;
    const unsigned* A = (z == 0) ? g_q16 : (z == 1) ? g_k16 : g_v16;
    const float* b    = (z == 0) ? bq : (z == 1) ? bk : bv;
    void* o           = (z == 0) ? (void*)g_Qh : (z == 1) ? (void*)g_Kh : (void*)g_Vh;
    gemm16_body(A, g_w16[z], b, o, z + 1);
}

__global__ __launch_bounds__(256, 1) void out_gemm_kernel(
    const float* __restrict__ bo, float* __restrict__ out)
{
    gemm16_body(g_Ch, g_w16[3], bo, (void*)out, 0);
}

// ---------------------------------------------------------------------------
// Flash attention fp16.  Q-tile 256 (halves K/V L2 traffic), 512 threads
// (16 warps, 16 q-rows each — proven per-warp economy), K-tile 64,
// 6-stage cp.async (uniform wait-4 + empty-commit tail), ldmatrix K/V frags,
// f32 ex2 softmax, l via ones-MMA, conditional rescale.
// ---------------------------------------------------------------------------
#define FL_KSTG 8192
#define FL_VSTG 8192
#define FL_STG  (FL_KSTG + FL_VSTG)
#define FL_NSTG 6
#define FL_SMEM (FL_NSTG * FL_STG)   // 98304

__global__ __launch_bounds__(512, 1) void flash_fp16_kernel()
{
    extern __shared__ char fsm[];
    const unsigned smBase = (unsigned)__cvta_generic_to_shared(fsm);

    const int t    = threadIdx.x;
    const int lane = t & 31;
    const int w    = t >> 5;          // 0..15
    const int gp   = lane >> 2;
    const int tg   = lane & 3;
    const int qr0  = w << 4;          // 0..240

    const int bh = blockIdx.y;
    const int q0 = blockIdx.x << 8;   // 256-row q tile

    const unsigned* Qw = g_Qh + (size_t)bh * S_ * 32;
    const unsigned* Kw = g_Kh + (size_t)bh * S_ * 32;
    const unsigned* Vw = g_Vh + (size_t)bh * HD_ * (S_ / 2);

    // loader: one 16B chunk each for K and V per thread (512 chunks = 64x8)
    const int kr = t >> 3;            // 0..63
    const int kj = t & 7;
    const unsigned coff = 128u * kr + ((16u * kj) ^ ((kr & 7) << 4));

#define FISSUE(st, it2) do {                                                     \
    const unsigned kbase = smBase + (st) * FL_STG;                               \
    const int kn = (it2) << 6;                                                   \
    CP16(kbase + coff, Kw + (size_t)(kn + kr) * 32 + 4 * kj);                    \
    CP16(kbase + FL_KSTG + coff, Vw + (size_t)kr * (S_ / 2) + (it2) * 32 + 4 * kj); \
    CP_COMMIT();                                                                 \
} while (0)

    // ---- Q fragments (natural layout, pre-scaled by SC_Q)
    unsigned qa[4][4];
#pragma unroll
    for (int s = 0; s < 4; s++) {
        const unsigned* r0 = Qw + (size_t)(q0 + qr0 + gp) * 32;
        const unsigned* r1 = Qw + (size_t)(q0 + qr0 + 8 + gp) * 32;
        qa[s][0] = r0[8 * s + tg];
        qa[s][1] = r1[8 * s + tg];
        qa[s][2] = r0[8 * s + tg + 4];
        qa[s][3] = r1[8 * s + tg + 4];
    }

    FISSUE(0, 0);
    FISSUE(1, 1);
    FISSUE(2, 2);
    FISSUE(3, 3);
    FISSUE(4, 4);

    const int kbrow0 = ((lane >> 4) << 3) + (lane & 7);
    const int kbsel  = ((lane >> 3) & 1) << 4;

    float m_i[2] = {-1e30f, -1e30f};
    float lacc[4] = {0.0f, 0.0f, 0.0f, 0.0f};
    float o[8][4];
#pragma unroll
    for (int dj = 0; dj < 8; dj++)
#pragma unroll
        for (int q = 0; q < 4; q++) o[dj][q] = 0.0f;

    for (int it = 0; it < 32; it++) {
        // committed groups before this wait: 5 + it; wait<=4 pending
        // guarantees groups 0..it complete (empty tail groups finish instantly)
        CP_WAIT4();
        __syncthreads();
        if (it + 5 < 32) { FISSUE((it + 5) % FL_NSTG, it + 5); }
        else             { CP_COMMIT(); }

        const unsigned kb = smBase + (it % FL_NSTG) * FL_STG;
        const unsigned vb = kb + FL_KSTG;

        // ---- S = Q K^T  (64 keys)
        float s[8][4];
#pragma unroll
        for (int nj = 0; nj < 8; nj++)
#pragma unroll
            for (int q = 0; q < 4; q++) s[nj][q] = 0.0f;

#pragma unroll
        for (int ks = 0; ks < 4; ks++) {
#pragma unroll
            for (int nj2 = 0; nj2 < 4; nj2++) {
                const int row = 16 * nj2 + kbrow0;
                const unsigned addr = kb + 128u * row + ((32 * ks + kbsel) ^ ((row & 7) << 4));
                unsigned b0, b1, b2, b3;
                ldsm4(b0, b1, b2, b3, addr);
                mma_f16(s[2 * nj2],     qa[ks], b0, b1);
                mma_f16(s[2 * nj2 + 1], qa[ks], b2, b3);
            }
        }

        // ---- softmax (max + conditional rescale)
#pragma unroll
        for (int h = 0; h < 2; h++) {
            float mx = fmaxf(s[0][2 * h], s[0][2 * h + 1]);
#pragma unroll
            for (int nj = 1; nj < 8; nj++)
                mx = fmaxf(mx, fmaxf(s[nj][2 * h], s[nj][2 * h + 1]));
            mx = fmaxf(mx, __shfl_xor_sync(0xffffffffu, mx, 1));
            mx = fmaxf(mx, __shfl_xor_sync(0xffffffffu, mx, 2));
            if (mx > m_i[h]) {
                const float corr = ex2(m_i[h] - mx);
                m_i[h] = mx;
                lacc[2 * h]     *= corr;
                lacc[2 * h + 1] *= corr;
#pragma unroll
                for (int dj = 0; dj < 8; dj++) {
                    o[dj][2 * h]     *= corr;
                    o[dj][2 * h + 1] *= corr;
                }
            }
        }

        // ---- P fragments (f32 ex2, packed)
        unsigned pa[4][4];
#pragma unroll
        for (int cp = 0; cp < 4; cp++) {
            pa[cp][0] = pack2(ex2(s[2 * cp][0] - m_i[0]),     ex2(s[2 * cp][1] - m_i[0]));
            pa[cp][1] = pack2(ex2(s[2 * cp][2] - m_i[1]),     ex2(s[2 * cp][3] - m_i[1]));
            pa[cp][2] = pack2(ex2(s[2 * cp + 1][0] - m_i[0]), ex2(s[2 * cp + 1][1] - m_i[0]));
            pa[cp][3] = pack2(ex2(s[2 * cp + 1][2] - m_i[1]), ex2(s[2 * cp + 1][3] - m_i[1]));
        }

        // ---- l += P @ ones (exact f32 sum of the fp16 P used below)
#pragma unroll
        for (int cp = 0; cp < 4; cp++)
            mma_f16(lacc, pa[cp], ONES2, ONES2);

        // ---- O += P @ V (ldmatrix V frags, natural layout)
#pragma unroll
        for (int cp = 0; cp < 4; cp++) {
#pragma unroll
            for (int dj2 = 0; dj2 < 4; dj2++) {
                const int row = 16 * dj2 + kbrow0;
                const unsigned addr = vb + 128u * row + ((32 * cp + kbsel) ^ ((row & 7) << 4));
                unsigned b0, b1, b2, b3;
                ldsm4(b0, b1, b2, b3, addr);
                mma_f16(o[2 * dj2],     pa[cp], b0, b1);
                mma_f16(o[2 * dj2 + 1], pa[cp], b2, b3);
            }
        }
    }
#undef FISSUE

    // ---- finalize (l = lacc[2h] is the full row sum)
    const int b_ = bh >> 4;
    const int hh = bh & 15;
#pragma unroll
    for (int h = 0; h < 2; h++) {
        const float inv = 1.0f / lacc[2 * h];
        const int srow = q0 + qr0 + gp + 8 * h;
        unsigned* co = g_Ch + ((size_t)(b_ * S_ + srow) << 9) + (hh << 5);
#pragma unroll
        for (int dj = 0; dj < 8; dj++)
            co[4 * dj + tg] = pack2(o[dj][2 * h] * inv, o[dj][2 * h + 1] * inv);
    }
}

// ---------------------------------------------------------------------------
extern "C" void kernel_launch(void* const* d_in, const int* in_sizes, int n_in,
                              void* d_out, int out_size)
{
    const float* query = (const float*)d_in[0];
    const float* key   = (const float*)d_in[1];
    const float* value = (const float*)d_in[2];
    const float* Wq    = (const float*)d_in[3];
    const float* bq    = (const float*)d_in[4];
    const float* Wk    = (const float*)d_in[5];
    const float* bk    = (const float*)d_in[6];
    const float* Wv    = (const float*)d_in[7];
    const float* bv    = (const float*)d_in[8];
    const float* Wo    = (const float*)d_in[9];
    const float* bo    = (const float*)d_in[10];

    static int smem_set = 0;
    if (!smem_set) {
        cudaFuncSetAttribute(qkv_gemm_kernel,
                             cudaFuncAttributeMaxDynamicSharedMemorySize, GM_SMEM);
        cudaFuncSetAttribute(out_gemm_kernel,
                             cudaFuncAttributeMaxDynamicSharedMemorySize, GM_SMEM);
        cudaFuncSetAttribute(flash_fp16_kernel,
                             cudaFuncAttributeMaxDynamicSharedMemorySize, FL_SMEM);
        smem_set = 1;
    }

    convert_kernel<<<dim3(2048, 1, 7), 256>>>(query, key, value, Wq, Wk, Wv, Wo);

    qkv_gemm_kernel<<<dim3(D_ / 128, M_ / 256, 3), 256, GM_SMEM>>>(bq, bk, bv);

    flash_fp16_kernel<<<dim3(S_ / 256, B_ * H_), 512, FL_SMEM>>>();

    out_gemm_kernel<<<dim3(D_ / 128, M_ / 256), 256, GM_SMEM>>>(bo, (float*)d_out);
}

// round 15
// speedup vs baseline: 1.0549x; 1.0549x over previous
#include <cuda_runtime.h>
#include <cuda_fp16.h>
#include <cstdint>

#define D_   1024
#define H_   16
#define HD_  64
#define B_   2
#define S_   2048
#define M_   (B_ * S_)          // 4096

// ---------------- scratch (device globals) ---------------------------------
__device__ unsigned g_q16[(size_t)M_ * D_ / 2];     // fp16 natural inputs
__device__ unsigned g_k16[(size_t)M_ * D_ / 2];
__device__ unsigned g_v16[(size_t)M_ * D_ / 2];
__device__ unsigned g_w16[4][(size_t)D_ * D_ / 2];  // Wq,Wk,Wv,Wo fp16
__device__ unsigned g_Qh[(size_t)M_ * D_ / 2];      // [B,H,S,32w] natural, *SC
__device__ unsigned g_Kh[(size_t)M_ * D_ / 2];      // [B,H,S,32w] natural
__device__ unsigned g_Vh[(size_t)M_ * D_ / 2];      // [B,H,64,S] natural (transposed)
__device__ unsigned g_Ch[(size_t)M_ * D_ / 2];      // ctx [M,512w] natural

#define SC_Q 0.18033688011112042f   /* 0.125 * log2(e) */

// ---------------------------------------------------------------------------
// helpers
// ---------------------------------------------------------------------------
__device__ __forceinline__ unsigned pack2(float lo, float hi) {
    unsigned r;
    asm("cvt.rn.f16x2.f32 %0, %1, %2;" : "=r"(r) : "f"(hi), "f"(lo));
    return r;
}
__device__ __forceinline__ float ex2(float x) {
    float y; asm("ex2.approx.ftz.f32 %0, %1;" : "=f"(y) : "f"(x)); return y;
}
__device__ __forceinline__ void mma_f16(float c[4], const unsigned a[4], unsigned b0, unsigned b1) {
    asm volatile(
        "mma.sync.aligned.m16n8k16.row.col.f32.f16.f16.f32 "
        "{%0,%1,%2,%3}, {%4,%5,%6,%7}, {%8,%9}, {%0,%1,%2,%3};\n"
        : "+f"(c[0]), "+f"(c[1]), "+f"(c[2]), "+f"(c[3])
        : "r"(a[0]), "r"(a[1]), "r"(a[2]), "r"(a[3]), "r"(b0), "r"(b1));
}
__device__ __forceinline__ void ldsm4(unsigned& r0, unsigned& r1, unsigned& r2, unsigned& r3,
                                      unsigned addr) {
    asm volatile("ldmatrix.sync.aligned.m8n8.x4.shared.b16 {%0,%1,%2,%3}, [%4];"
                 : "=r"(r0), "=r"(r1), "=r"(r2), "=r"(r3) : "r"(addr));
}
#define CP16(dst, src) \
    asm volatile("cp.async.cg.shared.global [%0], [%1], 16;" :: "r"(dst), "l"(src) : "memory")
#define CP_COMMIT() asm volatile("cp.async.commit_group;" ::: "memory")
#define CP_WAIT1()  asm volatile("cp.async.wait_group 1;" ::: "memory")
#define CP_WAIT0()  asm volatile("cp.async.wait_group 0;" ::: "memory")

// ---------------------------------------------------------------------------
// convert: fp32 -> fp16 natural (q,k,v + 4 weights)
// ---------------------------------------------------------------------------
__global__ __launch_bounds__(256) void convert_kernel(
    const float* __restrict__ q, const float* __restrict__ k, const float* __restrict__ v,
    const float* __restrict__ wq, const float* __restrict__ wk,
    const float* __restrict__ wv, const float* __restrict__ wo)
{
    const int z = blockIdx.z;
    const float* src;
    unsigned* dst;
    size_t n;
    switch (z) {
        case 0: src = q;  dst = g_q16;    n = (size_t)M_ * D_; break;
        case 1: src = k;  dst = g_k16;    n = (size_t)M_ * D_; break;
        case 2: src = v;  dst = g_v16;    n = (size_t)M_ * D_; break;
        case 3: src = wq; dst = g_w16[0]; n = (size_t)D_ * D_; break;
        case 4: src = wk; dst = g_w16[1]; n = (size_t)D_ * D_; break;
        case 5: src = wv; dst = g_w16[2]; n = (size_t)D_ * D_; break;
        default: src = wo; dst = g_w16[3]; n = (size_t)D_ * D_; break;
    }
    const size_t i8 = ((size_t)blockIdx.x * blockDim.x + threadIdx.x) * 8;
    if (i8 >= n) return;
    float4 f0 = *(const float4*)(src + i8);
    float4 f1 = *(const float4*)(src + i8 + 4);
    uint4 o = make_uint4(pack2(f0.x, f0.y), pack2(f0.z, f0.w),
                         pack2(f1.x, f1.y), pack2(f1.z, f1.w));
    *(uint4*)(dst + i8 / 2) = o;
}

// ---------------------------------------------------------------------------
// fp16 GEMM (round-9 config + explicit fragment double-buffering):
// CTA 128x128, 128 threads (4 warps 2x2, warp tile 64x64), BK=64 halves,
// 3-stage cp.async, SW128 smem, ldmatrix fragments prefetched one s-step
// ahead of their consuming MMAs.
// modes: 0 float out [M,D]; 1 Q natural *SC; 2 K natural; 3 V transposed nat.
// ---------------------------------------------------------------------------
#define GSTG   3
#define TILEB  16384
#define GM_SMEM (GSTG * 2 * TILEB)   // 98304

__device__ __forceinline__ void gemm16_body(
    const unsigned* __restrict__ Aw,
    const unsigned* __restrict__ Ww,
    const float* __restrict__ bias,
    void* __restrict__ outp,
    int mode)
{
    extern __shared__ char smc[];
    const unsigned smA = (unsigned)__cvta_generic_to_shared(smc);
    const unsigned smB = smA + GSTG * TILEB;

    const int t    = threadIdx.x;
    const int lane = t & 31;
    const int w    = t >> 5;
    const int gp   = lane >> 2;
    const int tg   = lane & 3;
    const int wm0  = (w >> 1) << 6;
    const int wn0  = (w & 1) << 6;

    const int m0 = blockIdx.y << 7;
    const int n0 = blockIdx.x << 7;

    const unsigned* Ab = Aw + (size_t)m0 * 512;
    const unsigned* Bb = Ww + (size_t)n0 * 512;

    const int lr = t >> 3;
    const int lc = t & 7;

    const int la15 = lane & 15;
    const int ahi  = (lane >> 4) << 4;
    const int bsel = ((lane >> 3) & 1) << 4;
    const int brow0 = wn0 + ((lane >> 4) << 3) + (lane & 7);

    int arow[4], akey[4];
#pragma unroll
    for (int mi = 0; mi < 4; mi++) {
        const int r = wm0 + 16 * mi + la15;
        arow[mi] = 128 * r;
        akey[mi] = (r & 7) << 4;
    }
    int brow[4], bkey[4];
#pragma unroll
    for (int nj2 = 0; nj2 < 4; nj2++) {
        const int r = brow0 + 16 * nj2;
        brow[nj2] = 128 * r;
        bkey[nj2] = (r & 7) << 4;
    }

    float acc[4][8][4];
#pragma unroll
    for (int mi = 0; mi < 4; mi++)
#pragma unroll
        for (int nj = 0; nj < 8; nj++)
#pragma unroll
            for (int q = 0; q < 4; q++) acc[mi][nj][q] = 0.0f;

#define GISSUE(st, kc) do {                                                    \
    const unsigned da = smA + (st) * TILEB;                                    \
    const unsigned db = smB + (st) * TILEB;                                    \
    _Pragma("unroll")                                                          \
    for (int i = 0; i < 8; i++) {                                              \
        const int row = lr + 16 * i;                                           \
        const unsigned off = 128u * row + ((16u * lc) ^ ((row & 7) << 4));     \
        CP16(da + off, Ab + (size_t)row * 512 + (kc) * 32 + 4 * lc);           \
        CP16(db + off, Bb + (size_t)row * 512 + (kc) * 32 + 4 * lc);           \
    }                                                                          \
    CP_COMMIT();                                                               \
} while (0)

// fragment prefetch for s-step (into buffer buf)
#define LOADFRAG(buf, s) do {                                                  \
    _Pragma("unroll")                                                          \
    for (int mi = 0; mi < 4; mi++)                                             \
        ldsm4(a[buf][mi][0], a[buf][mi][1], a[buf][mi][2], a[buf][mi][3],      \
              ab + arow[mi] + ((32 * (s) + ahi) ^ akey[mi]));                  \
    _Pragma("unroll")                                                          \
    for (int nj2 = 0; nj2 < 4; nj2++)                                          \
        ldsm4(bfr[buf][nj2][0], bfr[buf][nj2][1], bfr[buf][nj2][2],            \
              bfr[buf][nj2][3],                                                \
              bb + brow[nj2] + ((32 * (s) + bsel) ^ bkey[nj2]));               \
} while (0)

    GISSUE(0, 0);
    GISSUE(1, 1);

    unsigned a[2][4][4], bfr[2][4][4];

    for (int kc = 0; kc < 16; kc++) {
        if (kc == 15) { CP_WAIT0(); } else { CP_WAIT1(); }
        __syncthreads();
        if (kc + 2 < 16) {
            const int st = (kc + 2) % 3;
            GISSUE(st, kc + 2);
        }

        const unsigned ab = smA + (kc % 3) * TILEB;
        const unsigned bb = smB + (kc % 3) * TILEB;

        LOADFRAG(0, 0);
#pragma unroll
        for (int s = 0; s < 4; s++) {
            const int cur = s & 1;
            if (s < 3) LOADFRAG(cur ^ 1, s + 1);
#pragma unroll
            for (int nj2 = 0; nj2 < 4; nj2++) {
#pragma unroll
                for (int mi = 0; mi < 4; mi++) {
                    mma_f16(acc[mi][2 * nj2],     a[cur][mi], bfr[cur][nj2][0], bfr[cur][nj2][1]);
                    mma_f16(acc[mi][2 * nj2 + 1], a[cur][mi], bfr[cur][nj2][2], bfr[cur][nj2][3]);
                }
            }
        }
    }
#undef LOADFRAG
#undef GISSUE

    // ---- epilogue
#pragma unroll
    for (int mi = 0; mi < 4; mi++) {
#pragma unroll
        for (int h = 0; h < 2; h++) {
            const int m  = m0 + wm0 + 16 * mi + gp + 8 * h;
            const int b_ = m >> 11;
            const int s  = m & (S_ - 1);
#pragma unroll
            for (int nj = 0; nj < 8; nj++) {
                const int e  = n0 + wn0 + 8 * nj + 2 * tg;
                const float vx = acc[mi][nj][2 * h]     + bias[e];
                const float vy = acc[mi][nj][2 * h + 1] + bias[e + 1];
                if (mode == 0) {
                    *(float2*)((float*)outp + (size_t)m * D_ + e) = make_float2(vx, vy);
                } else if (mode == 1 || mode == 2) {
                    const int hh = e >> 6, hd = e & 63;
                    const float sc = (mode == 1) ? SC_Q : 1.0f;
                    ((unsigned*)outp)[(((size_t)(b_ * H_ + hh) * S_ + s) << 5) + (hd >> 1)] =
                        pack2(vx * sc, vy * sc);
                } else {
                    // V: natural transposed [b,h,hd][s]
                    const int hh = e >> 6, hd = e & 63;
                    __half* vo = (__half*)outp + (((size_t)(b_ * H_ + hh) * HD_ + hd)) * S_ + s;
                    vo[0]  = __float2half_rn(vx);
                    vo[S_] = __float2half_rn(vy);
                }
            }
        }
    }
}

__global__ __launch_bounds__(128, 2) void qkv_gemm_kernel(
    const float* __restrict__ bq, const float* __restrict__ bk, const float* __restrict__ bv)
{
    const int z = blockIdx.z;
    const unsigned* A = (z == 0) ? g_q16 : (z == 1) ? g_k16 : g_v16;
    const float* b    = (z == 0) ? bq : (z == 1) ? bk : bv;
    void* o           = (z == 0) ? (void*)g_Qh : (z == 1) ? (void*)g_Kh : (void*)g_Vh;
    gemm16_body(A, g_w16[z], b, o, z + 1);
}

__global__ __launch_bounds__(128, 2) void out_gemm_kernel(
    const float* __restrict__ bo, float* __restrict__ out)
{
    gemm16_body(g_Ch, g_w16[3], bo, (void*)out, 0);
}

// ---------------------------------------------------------------------------
// Flash attention fp16 (round-9 proven version): 256 threads (8 warps),
// Q-tile 128 (16 rows/warp), K-tile 64, 3-stage cp.async, ldmatrix K and V
// frags, deferred l-sum, conditional rescale.
// ---------------------------------------------------------------------------
#define FL_KSTG 8192
#define FL_VSTG 8192
#define FL_SMEM (3 * (FL_KSTG + FL_VSTG))   // 49152

__global__ __launch_bounds__(256, 2) void flash_fp16_kernel()
{
    extern __shared__ char fsm[];
    const unsigned smK = (unsigned)__cvta_generic_to_shared(fsm);
    const unsigned smV = smK + 3 * FL_KSTG;

    const int t    = threadIdx.x;
    const int lane = t & 31;
    const int w    = t >> 5;
    const int gp   = lane >> 2;
    const int tg   = lane & 3;
    const int qr0  = w << 4;

    const int bh = blockIdx.y;
    const int q0 = blockIdx.x << 7;

    const unsigned* Qw = g_Qh + (size_t)bh * S_ * 32;
    const unsigned* Kw = g_Kh + (size_t)bh * S_ * 32;
    const unsigned* Vw = g_Vh + (size_t)bh * HD_ * (S_ / 2);

    const int kr0 = t >> 3;
    const int kj  = t & 7;
    const unsigned off0 = 128u * kr0 + ((16u * kj) ^ ((kr0 & 7) << 4));
    const unsigned off1 = 128u * (kr0 + 32) + ((16u * kj) ^ (((kr0 + 32) & 7) << 4));

#define FISSUE(st, it2) do {                                                     \
    const int kn = (it2) << 6;                                                   \
    CP16(smK + (st) * FL_KSTG + off0, Kw + (size_t)(kn + kr0) * 32 + 4 * kj);    \
    CP16(smK + (st) * FL_KSTG + off1, Kw + (size_t)(kn + kr0 + 32) * 32 + 4 * kj); \
    CP16(smV + (st) * FL_VSTG + off0,                                            \
         Vw + (size_t)kr0 * (S_ / 2) + (it2) * 32 + 4 * kj);                     \
    CP16(smV + (st) * FL_VSTG + off1,                                            \
         Vw + (size_t)(kr0 + 32) * (S_ / 2) + (it2) * 32 + 4 * kj);              \
    CP_COMMIT();                                                                 \
} while (0)

    // ---- Q fragments (natural layout, pre-scaled by SC_Q)
    unsigned qa[4][4];
#pragma unroll
    for (int s = 0; s < 4; s++) {
        const unsigned* r0 = Qw + (size_t)(q0 + qr0 + gp) * 32;
        const unsigned* r1 = Qw + (size_t)(q0 + qr0 + 8 + gp) * 32;
        qa[s][0] = r0[8 * s + tg];
        qa[s][1] = r1[8 * s + tg];
        qa[s][2] = r0[8 * s + tg + 4];
        qa[s][3] = r1[8 * s + tg + 4];
    }

    FISSUE(0, 0);
    FISSUE(1, 1);

    const int kbrow0 = ((lane >> 4) << 3) + (lane & 7);
    const int kbsel  = ((lane >> 3) & 1) << 4;

    float m_i[2] = {-1e30f, -1e30f};
    float l_i[2] = {0.0f, 0.0f};
    float o[8][4];
#pragma unroll
    for (int dj = 0; dj < 8; dj++)
#pragma unroll
        for (int q = 0; q < 4; q++) o[dj][q] = 0.0f;

    for (int it = 0; it < 32; it++) {
        if (it == 31) { CP_WAIT0(); } else { CP_WAIT1(); }
        __syncthreads();
        if (it + 2 < 32) FISSUE((it + 2) % 3, it + 2);

        const unsigned kb = smK + (it % 3) * FL_KSTG;
        const unsigned vb = smV + (it % 3) * FL_VSTG;

        // ---- S = Q K^T  (64 keys)
        float s[8][4];
#pragma unroll
        for (int nj = 0; nj < 8; nj++)
#pragma unroll
            for (int q = 0; q < 4; q++) s[nj][q] = 0.0f;

#pragma unroll
        for (int ks = 0; ks < 4; ks++) {
#pragma unroll
            for (int nj2 = 0; nj2 < 4; nj2++) {
                const int row = 16 * nj2 + kbrow0;
                const unsigned addr = kb + 128u * row + ((32 * ks + kbsel) ^ ((row & 7) << 4));
                unsigned b0, b1, b2, b3;
                ldsm4(b0, b1, b2, b3, addr);
                mma_f16(s[2 * nj2],     qa[ks], b0, b1);
                mma_f16(s[2 * nj2 + 1], qa[ks], b2, b3);
            }
        }

        // ---- online softmax (exp2 domain; deferred l-sum; cond. rescale)
#pragma unroll
        for (int h = 0; h < 2; h++) {
            float mx = fmaxf(s[0][2 * h], s[0][2 * h + 1]);
#pragma unroll
            for (int nj = 1; nj < 8; nj++)
                mx = fmaxf(mx, fmaxf(s[nj][2 * h], s[nj][2 * h + 1]));
            mx = fmaxf(mx, __shfl_xor_sync(0xffffffffu, mx, 1));
            mx = fmaxf(mx, __shfl_xor_sync(0xffffffffu, mx, 2));
            if (mx > m_i[h]) {
                const float corr = ex2(m_i[h] - mx);
                m_i[h] = mx;
                l_i[h] *= corr;
#pragma unroll
                for (int dj = 0; dj < 8; dj++) {
                    o[dj][2 * h]     *= corr;
                    o[dj][2 * h + 1] *= corr;
                }
            }
            float rs = 0.0f;
#pragma unroll
            for (int nj = 0; nj < 8; nj++) {
                s[nj][2 * h]     = ex2(s[nj][2 * h] - m_i[h]);
                s[nj][2 * h + 1] = ex2(s[nj][2 * h + 1] - m_i[h]);
                rs += s[nj][2 * h] + s[nj][2 * h + 1];
            }
            l_i[h] += rs;
        }

        // ---- P fragments
        unsigned pa[4][4];
#pragma unroll
        for (int cp = 0; cp < 4; cp++) {
            pa[cp][0] = pack2(s[2 * cp][0],     s[2 * cp][1]);
            pa[cp][1] = pack2(s[2 * cp][2],     s[2 * cp][3]);
            pa[cp][2] = pack2(s[2 * cp + 1][0], s[2 * cp + 1][1]);
            pa[cp][3] = pack2(s[2 * cp + 1][2], s[2 * cp + 1][3]);
        }

        // ---- O += P @ V (ldmatrix V frags, natural layout)
#pragma unroll
        for (int cp = 0; cp < 4; cp++) {
#pragma unroll
            for (int dj2 = 0; dj2 < 4; dj2++) {
                const int row = 16 * dj2 + kbrow0;
                const unsigned addr = vb + 128u * row + ((32 * cp + kbsel) ^ ((row & 7) << 4));
                unsigned b0, b1, b2, b3;
                ldsm4(b0, b1, b2, b3, addr);
                mma_f16(o[2 * dj2],     pa[cp], b0, b1);
                mma_f16(o[2 * dj2 + 1], pa[cp], b2, b3);
            }
        }
    }
#undef FISSUE

    // ---- finalize l, write ctx natural fp16
    const int b_ = bh >> 4;
    const int hh = bh & 15;
#pragma unroll
    for (int h = 0; h < 2; h++) {
        float l = l_i[h];
        l += __shfl_xor_sync(0xffffffffu, l, 1);
        l += __shfl_xor_sync(0xffffffffu, l, 2);
        const float inv = 1.0f / l;
        const int srow = q0 + qr0 + gp + 8 * h;
        unsigned* co = g_Ch + ((size_t)(b_ * S_ + srow) << 9) + (hh << 5);
#pragma unroll
        for (int dj = 0; dj < 8; dj++)
            co[4 * dj + tg] = pack2(o[dj][2 * h] * inv, o[dj][2 * h + 1] * inv);
    }
}

// ---------------------------------------------------------------------------
extern "C" void kernel_launch(void* const* d_in, const int* in_sizes, int n_in,
                              void* d_out, int out_size)
{
    const float* query = (const float*)d_in[0];
    const float* key   = (const float*)d_in[1];
    const float* value = (const float*)d_in[2];
    const float* Wq    = (const float*)d_in[3];
    const float* bq    = (const float*)d_in[4];
    const float* Wk    = (const float*)d_in[5];
    const float* bk    = (const float*)d_in[6];
    const float* Wv    = (const float*)d_in[7];
    const float* bv    = (const float*)d_in[8];
    const float* Wo    = (const float*)d_in[9];
    const float* bo    = (const float*)d_in[10];

    static int smem_set = 0;
    if (!smem_set) {
        cudaFuncSetAttribute(qkv_gemm_kernel,
                             cudaFuncAttributeMaxDynamicSharedMemorySize, GM_SMEM);
        cudaFuncSetAttribute(out_gemm_kernel,
                             cudaFuncAttributeMaxDynamicSharedMemorySize, GM_SMEM);
        cudaFuncSetAttribute(flash_fp16_kernel,
                             cudaFuncAttributeMaxDynamicSharedMemorySize, FL_SMEM);
        smem_set = 1;
    }

    convert_kernel<<<dim3(2048, 1, 7), 256>>>(query, key, value, Wq, Wk, Wv, Wo);

    qkv_gemm_kernel<<<dim3(D_ / 128, M_ / 128, 3), 128, GM_SMEM>>>(bq, bk, bv);

    flash_fp16_kernel<<<dim3(S_ / 128, B_ * H_), 256, FL_SMEM>>>();

    out_gemm_kernel<<<dim3(D_ / 128, M_ / 128), 128, GM_SMEM>>>(bo, (float*)d_out);
}

// round 16
// speedup vs baseline: 1.0930x; 1.0362x over previous
#include <cuda_runtime.h>
#include <cuda_fp16.h>
#include <cstdint>

#define D_   1024
#define H_   16
#define HD_  64
#define B_   2
#define S_   2048
#define M_   (B_ * S_)          // 4096

// ---------------- scratch (device globals) ---------------------------------
__device__ unsigned g_q16[(size_t)M_ * D_ / 2];     // fp16 natural inputs
__device__ unsigned g_k16[(size_t)M_ * D_ / 2];
__device__ unsigned g_v16[(size_t)M_ * D_ / 2];
__device__ unsigned g_w16[4][(size_t)D_ * D_ / 2];  // Wq,Wk,Wv,Wo fp16
__device__ unsigned g_Qh[(size_t)M_ * D_ / 2];      // [B,H,S,32w] natural, *SC
__device__ unsigned g_Kh[(size_t)M_ * D_ / 2];      // [B,H,S,32w] natural
__device__ unsigned g_Vh[(size_t)M_ * D_ / 2];      // [B,H,64,S] natural (transposed)
__device__ unsigned g_Ch[(size_t)M_ * D_ / 2];      // ctx [M,512w] natural

#define SC_Q 0.18033688011112042f   /* 0.125 * log2(e) */

// ---------------------------------------------------------------------------
// helpers
// ---------------------------------------------------------------------------
__device__ __forceinline__ unsigned pack2(float lo, float hi) {
    unsigned r;
    asm("cvt.rn.f16x2.f32 %0, %1, %2;" : "=r"(r) : "f"(hi), "f"(lo));
    return r;
}
__device__ __forceinline__ float ex2(float x) {
    float y; asm("ex2.approx.ftz.f32 %0, %1;" : "=f"(y) : "f"(x)); return y;
}
__device__ __forceinline__ void mma_f16(float c[4], const unsigned a[4], unsigned b0, unsigned b1) {
    asm volatile(
        "mma.sync.aligned.m16n8k16.row.col.f32.f16.f16.f32 "
        "{%0,%1,%2,%3}, {%4,%5,%6,%7}, {%8,%9}, {%0,%1,%2,%3};\n"
        : "+f"(c[0]), "+f"(c[1]), "+f"(c[2]), "+f"(c[3])
        : "r"(a[0]), "r"(a[1]), "r"(a[2]), "r"(a[3]), "r"(b0), "r"(b1));
}
__device__ __forceinline__ void ldsm4(unsigned& r0, unsigned& r1, unsigned& r2, unsigned& r3,
                                      unsigned addr) {
    asm volatile("ldmatrix.sync.aligned.m8n8.x4.shared.b16 {%0,%1,%2,%3}, [%4];"
                 : "=r"(r0), "=r"(r1), "=r"(r2), "=r"(r3) : "r"(addr));
}
#define CP16(dst, src) \
    asm volatile("cp.async.cg.shared.global [%0], [%1], 16;" :: "r"(dst), "l"(src) : "memory")
#define CP_COMMIT() asm volatile("cp.async.commit_group;" ::: "memory")
#define CP_WAIT2()  asm volatile("cp.async.wait_group 2;" ::: "memory")
#define CP_WAIT1()  asm volatile("cp.async.wait_group 1;" ::: "memory")
#define CP_WAIT0()  asm volatile("cp.async.wait_group 0;" ::: "memory")

// ---------------------------------------------------------------------------
// convert: fp32 -> fp16 natural (q,k,v + 4 weights)
// ---------------------------------------------------------------------------
__global__ __launch_bounds__(256) void convert_kernel(
    const float* __restrict__ q, const float* __restrict__ k, const float* __restrict__ v,
    const float* __restrict__ wq, const float* __restrict__ wk,
    const float* __restrict__ wv, const float* __restrict__ wo)
{
    const int z = blockIdx.z;
    const float* src;
    unsigned* dst;
    size_t n;
    switch (z) {
        case 0: src = q;  dst = g_q16;    n = (size_t)M_ * D_; break;
        case 1: src = k;  dst = g_k16;    n = (size_t)M_ * D_; break;
        case 2: src = v;  dst = g_v16;    n = (size_t)M_ * D_; break;
        case 3: src = wq; dst = g_w16[0]; n = (size_t)D_ * D_; break;
        case 4: src = wk; dst = g_w16[1]; n = (size_t)D_ * D_; break;
        case 5: src = wv; dst = g_w16[2]; n = (size_t)D_ * D_; break;
        default: src = wo; dst = g_w16[3]; n = (size_t)D_ * D_; break;
    }
    const size_t i8 = ((size_t)blockIdx.x * blockDim.x + threadIdx.x) * 8;
    if (i8 >= n) return;
    float4 f0 = *(const float4*)(src + i8);
    float4 f1 = *(const float4*)(src + i8 + 4);
    uint4 o = make_uint4(pack2(f0.x, f0.y), pack2(f0.z, f0.w),
                         pack2(f1.x, f1.y), pack2(f1.z, f1.w));
    *(uint4*)(dst + i8 / 2) = o;
}

// ---------------------------------------------------------------------------
// fp16 GEMM (round-9 champion config, verbatim): CTA 128x128, 128 threads
// (4 warps 2x2, warp tile 64x64), BK=64 halves, 3-stage cp.async, SW128
// smem, ldmatrix fragments.
// modes: 0 float out [M,D]; 1 Q natural *SC; 2 K natural; 3 V transposed nat.
// ---------------------------------------------------------------------------
#define GSTG   3
#define TILEB  16384
#define GM_SMEM (GSTG * 2 * TILEB)   // 98304

__device__ __forceinline__ void gemm16_body(
    const unsigned* __restrict__ Aw,
    const unsigned* __restrict__ Ww,
    const float* __restrict__ bias,
    void* __restrict__ outp,
    int mode)
{
    extern __shared__ char smc[];
    const unsigned smA = (unsigned)__cvta_generic_to_shared(smc);
    const unsigned smB = smA + GSTG * TILEB;

    const int t    = threadIdx.x;
    const int lane = t & 31;
    const int w    = t >> 5;
    const int gp   = lane >> 2;
    const int tg   = lane & 3;
    const int wm0  = (w >> 1) << 6;
    const int wn0  = (w & 1) << 6;

    const int m0 = blockIdx.y << 7;
    const int n0 = blockIdx.x << 7;

    const unsigned* Ab = Aw + (size_t)m0 * 512;
    const unsigned* Bb = Ww + (size_t)n0 * 512;

    const int lr = t >> 3;
    const int lc = t & 7;

    const int la15 = lane & 15;
    const int ahi  = (lane >> 4) << 4;
    const int bsel = ((lane >> 3) & 1) << 4;
    const int brow0 = wn0 + ((lane >> 4) << 3) + (lane & 7);

    int arow[4], akey[4];
#pragma unroll
    for (int mi = 0; mi < 4; mi++) {
        const int r = wm0 + 16 * mi + la15;
        arow[mi] = 128 * r;
        akey[mi] = (r & 7) << 4;
    }

    float acc[4][8][4];
#pragma unroll
    for (int mi = 0; mi < 4; mi++)
#pragma unroll
        for (int nj = 0; nj < 8; nj++)
#pragma unroll
            for (int q = 0; q < 4; q++) acc[mi][nj][q] = 0.0f;

#define GISSUE(st, kc) do {                                                    \
    const unsigned da = smA + (st) * TILEB;                                    \
    const unsigned db = smB + (st) * TILEB;                                    \
    _Pragma("unroll")                                                          \
    for (int i = 0; i < 8; i++) {                                              \
        const int row = lr + 16 * i;                                           \
        const unsigned off = 128u * row + ((16u * lc) ^ ((row & 7) << 4));     \
        CP16(da + off, Ab + (size_t)row * 512 + (kc) * 32 + 4 * lc);           \
        CP16(db + off, Bb + (size_t)row * 512 + (kc) * 32 + 4 * lc);           \
    }                                                                          \
    CP_COMMIT();                                                               \
} while (0)

    GISSUE(0, 0);
    GISSUE(1, 1);

    for (int kc = 0; kc < 16; kc++) {
        if (kc == 15) { CP_WAIT0(); } else { CP_WAIT1(); }
        __syncthreads();
        if (kc + 2 < 16) {
            const int st = (kc + 2) % 3;
            GISSUE(st, kc + 2);
        }

        const unsigned ab = smA + (kc % 3) * TILEB;
        const unsigned bb = smB + (kc % 3) * TILEB;

#pragma unroll
        for (int s = 0; s < 4; s++) {
            unsigned a[4][4];
#pragma unroll
            for (int mi = 0; mi < 4; mi++) {
                const unsigned addr = ab + arow[mi] + ((32 * s + ahi) ^ akey[mi]);
                ldsm4(a[mi][0], a[mi][1], a[mi][2], a[mi][3], addr);
            }
#pragma unroll
            for (int nj2 = 0; nj2 < 4; nj2++) {
                const int row = brow0 + 16 * nj2;
                const unsigned addr = bb + 128u * row + ((32 * s + bsel) ^ ((row & 7) << 4));
                unsigned b0, b1, b2, b3;
                ldsm4(b0, b1, b2, b3, addr);
#pragma unroll
                for (int mi = 0; mi < 4; mi++) {
                    mma_f16(acc[mi][2 * nj2],     a[mi], b0, b1);
                    mma_f16(acc[mi][2 * nj2 + 1], a[mi], b2, b3);
                }
            }
        }
    }
#undef GISSUE

    // ---- epilogue
#pragma unroll
    for (int mi = 0; mi < 4; mi++) {
#pragma unroll
        for (int h = 0; h < 2; h++) {
            const int m  = m0 + wm0 + 16 * mi + gp + 8 * h;
            const int b_ = m >> 11;
            const int s  = m & (S_ - 1);
#pragma unroll
            for (int nj = 0; nj < 8; nj++) {
                const int e  = n0 + wn0 + 8 * nj + 2 * tg;
                const float vx = acc[mi][nj][2 * h]     + bias[e];
                const float vy = acc[mi][nj][2 * h + 1] + bias[e + 1];
                if (mode == 0) {
                    *(float2*)((float*)outp + (size_t)m * D_ + e) = make_float2(vx, vy);
                } else if (mode == 1 || mode == 2) {
                    const int hh = e >> 6, hd = e & 63;
                    const float sc = (mode == 1) ? SC_Q : 1.0f;
                    ((unsigned*)outp)[(((size_t)(b_ * H_ + hh) * S_ + s) << 5) + (hd >> 1)] =
                        pack2(vx * sc, vy * sc);
                } else {
                    // V: natural transposed [b,h,hd][s]
                    const int hh = e >> 6, hd = e & 63;
                    __half* vo = (__half*)outp + (((size_t)(b_ * H_ + hh) * HD_ + hd)) * S_ + s;
                    vo[0]  = __float2half_rn(vx);
                    vo[S_] = __float2half_rn(vy);
                }
            }
        }
    }
}

__global__ __launch_bounds__(128, 2) void qkv_gemm_kernel(
    const float* __restrict__ bq, const float* __restrict__ bk, const float* __restrict__ bv)
{
    const int z = blockIdx.z;
    const unsigned* A = (z == 0) ? g_q16 : (z == 1) ? g_k16 : g_v16;
    const float* b    = (z == 0) ? bq : (z == 1) ? bk : bv;
    void* o           = (z == 0) ? (void*)g_Qh : (z == 1) ? (void*)g_Kh : (void*)g_Vh;
    gemm16_body(A, g_w16[z], b, o, z + 1);
}

__global__ __launch_bounds__(128, 2) void out_gemm_kernel(
    const float* __restrict__ bo, float* __restrict__ out)
{
    gemm16_body(g_Ch, g_w16[3], bo, (void*)out, 0);
}

// ---------------------------------------------------------------------------
// Flash attention fp16 (round-9 champion + 4-stage pipeline): 256 threads
// (8 warps), Q-tile 128 (16 rows/warp), K-tile 64, 4-stage cp.async
// (uniform wait-2 + always-commit tail), ldmatrix K and V frags,
// deferred l-sum, conditional rescale.
// ---------------------------------------------------------------------------
#define FL_KSTG 8192
#define FL_VSTG 8192
#define FL_STG  (FL_KSTG + FL_VSTG)
#define FL_NSTG 4
#define FL_SMEM (FL_NSTG * FL_STG)   // 65536

__global__ __launch_bounds__(256, 2) void flash_fp16_kernel()
{
    extern __shared__ char fsm[];
    const unsigned smBase = (unsigned)__cvta_generic_to_shared(fsm);

    const int t    = threadIdx.x;
    const int lane = t & 31;
    const int w    = t >> 5;
    const int gp   = lane >> 2;
    const int tg   = lane & 3;
    const int qr0  = w << 4;

    const int bh = blockIdx.y;
    const int q0 = blockIdx.x << 7;

    const unsigned* Qw = g_Qh + (size_t)bh * S_ * 32;
    const unsigned* Kw = g_Kh + (size_t)bh * S_ * 32;
    const unsigned* Vw = g_Vh + (size_t)bh * HD_ * (S_ / 2);

    const int kr0 = t >> 3;
    const int kj  = t & 7;
    const unsigned off0 = 128u * kr0 + ((16u * kj) ^ ((kr0 & 7) << 4));
    const unsigned off1 = 128u * (kr0 + 32) + ((16u * kj) ^ (((kr0 + 32) & 7) << 4));

#define FISSUE(st, it2) do {                                                     \
    const unsigned kbase = smBase + (st) * FL_STG;                               \
    const unsigned vbase = kbase + FL_KSTG;                                      \
    const int kn = (it2) << 6;                                                   \
    CP16(kbase + off0, Kw + (size_t)(kn + kr0) * 32 + 4 * kj);                   \
    CP16(kbase + off1, Kw + (size_t)(kn + kr0 + 32) * 32 + 4 * kj);              \
    CP16(vbase + off0, Vw + (size_t)kr0 * (S_ / 2) + (it2) * 32 + 4 * kj);       \
    CP16(vbase + off1, Vw + (size_t)(kr0 + 32) * (S_ / 2) + (it2) * 32 + 4 * kj);\
    CP_COMMIT();                                                                 \
} while (0)

    // ---- Q fragments (natural layout, pre-scaled by SC_Q)
    unsigned qa[4][4];
#pragma unroll
    for (int s = 0; s < 4; s++) {
        const unsigned* r0 = Qw + (size_t)(q0 + qr0 + gp) * 32;
        const unsigned* r1 = Qw + (size_t)(q0 + qr0 + 8 + gp) * 32;
        qa[s][0] = r0[8 * s + tg];
        qa[s][1] = r1[8 * s + tg];
        qa[s][2] = r0[8 * s + tg + 4];
        qa[s][3] = r1[8 * s + tg + 4];
    }

    FISSUE(0, 0);
    FISSUE(1, 1);
    FISSUE(2, 2);

    const int kbrow0 = ((lane >> 4) << 3) + (lane & 7);
    const int kbsel  = ((lane >> 3) & 1) << 4;

    float m_i[2] = {-1e30f, -1e30f};
    float l_i[2] = {0.0f, 0.0f};
    float o[8][4];
#pragma unroll
    for (int dj = 0; dj < 8; dj++)
#pragma unroll
        for (int q = 0; q < 4; q++) o[dj][q] = 0.0f;

    for (int it = 0; it < 32; it++) {
        // committed so far = 3 + it; wait <=2 pending => groups 0..it complete
        CP_WAIT2();
        __syncthreads();
        if (it + 3 < 32) { FISSUE((it + 3) & 3, it + 3); }
        else             { CP_COMMIT(); }   // empty group keeps wait math uniform

        const unsigned kb = smBase + (it & 3) * FL_STG;
        const unsigned vb = kb + FL_KSTG;

        // ---- S = Q K^T  (64 keys)
        float s[8][4];
#pragma unroll
        for (int nj = 0; nj < 8; nj++)
#pragma unroll
            for (int q = 0; q < 4; q++) s[nj][q] = 0.0f;

#pragma unroll
        for (int ks = 0; ks < 4; ks++) {
#pragma unroll
            for (int nj2 = 0; nj2 < 4; nj2++) {
                const int row = 16 * nj2 + kbrow0;
                const unsigned addr = kb + 128u * row + ((32 * ks + kbsel) ^ ((row & 7) << 4));
                unsigned b0, b1, b2, b3;
                ldsm4(b0, b1, b2, b3, addr);
                mma_f16(s[2 * nj2],     qa[ks], b0, b1);
                mma_f16(s[2 * nj2 + 1], qa[ks], b2, b3);
            }
        }

        // ---- online softmax (exp2 domain; deferred l-sum; cond. rescale)
#pragma unroll
        for (int h = 0; h < 2; h++) {
            float mx = fmaxf(s[0][2 * h], s[0][2 * h + 1]);
#pragma unroll
            for (int nj = 1; nj < 8; nj++)
                mx = fmaxf(mx, fmaxf(s[nj][2 * h], s[nj][2 * h + 1]));
            mx = fmaxf(mx, __shfl_xor_sync(0xffffffffu, mx, 1));
            mx = fmaxf(mx, __shfl_xor_sync(0xffffffffu, mx, 2));
            if (mx > m_i[h]) {
                const float corr = ex2(m_i[h] - mx);
                m_i[h] = mx;
                l_i[h] *= corr;
#pragma unroll
                for (int dj = 0; dj < 8; dj++) {
                    o[dj][2 * h]     *= corr;
                    o[dj][2 * h + 1] *= corr;
                }
            }
            float rs = 0.0f;
#pragma unroll
            for (int nj = 0; nj < 8; nj++) {
                s[nj][2 * h]     = ex2(s[nj][2 * h] - m_i[h]);
                s[nj][2 * h + 1] = ex2(s[nj][2 * h + 1] - m_i[h]);
                rs += s[nj][2 * h] + s[nj][2 * h + 1];
            }
            l_i[h] += rs;
        }

        // ---- P fragments
        unsigned pa[4][4];
#pragma unroll
        for (int cp = 0; cp < 4; cp++) {
            pa[cp][0] = pack2(s[2 * cp][0],     s[2 * cp][1]);
            pa[cp][1] = pack2(s[2 * cp][2],     s[2 * cp][3]);
            pa[cp][2] = pack2(s[2 * cp + 1][0], s[2 * cp + 1][1]);
            pa[cp][3] = pack2(s[2 * cp + 1][2], s[2 * cp + 1][3]);
        }

        // ---- O += P @ V (ldmatrix V frags, natural layout)
#pragma unroll
        for (int cp = 0; cp < 4; cp++) {
#pragma unroll
            for (int dj2 = 0; dj2 < 4; dj2++) {
                const int row = 16 * dj2 + kbrow0;
                const unsigned addr = vb + 128u * row + ((32 * cp + kbsel) ^ ((row & 7) << 4));
                unsigned b0, b1, b2, b3;
                ldsm4(b0, b1, b2, b3, addr);
                mma_f16(o[2 * dj2],     pa[cp], b0, b1);
                mma_f16(o[2 * dj2 + 1], pa[cp], b2, b3);
            }
        }
    }
#undef FISSUE

    // ---- finalize l, write ctx natural fp16
    const int b_ = bh >> 4;
    const int hh = bh & 15;
#pragma unroll
    for (int h = 0; h < 2; h++) {
        float l = l_i[h];
        l += __shfl_xor_sync(0xffffffffu, l, 1);
        l += __shfl_xor_sync(0xffffffffu, l, 2);
        const float inv = 1.0f / l;
        const int srow = q0 + qr0 + gp + 8 * h;
        unsigned* co = g_Ch + ((size_t)(b_ * S_ + srow) << 9) + (hh << 5);
#pragma unroll
        for (int dj = 0; dj < 8; dj++)
            co[4 * dj + tg] = pack2(o[dj][2 * h] * inv, o[dj][2 * h + 1] * inv);
    }
}

// ---------------------------------------------------------------------------
extern "C" void kernel_launch(void* const* d_in, const int* in_sizes, int n_in,
                              void* d_out, int out_size)
{
    const float* query = (const float*)d_in[0];
    const float* key   = (const float*)d_in[1];
    const float* value = (const float*)d_in[2];
    const float* Wq    = (const float*)d_in[3];
    const float* bq    = (const float*)d_in[4];
    const float* Wk    = (const float*)d_in[5];
    const float* bk    = (const float*)d_in[6];
    const float* Wv    = (const float*)d_in[7];
    const float* bv    = (const float*)d_in[8];
    const float* Wo    = (const float*)d_in[9];
    const float* bo    = (const float*)d_in[10];

    static int smem_set = 0;
    if (!smem_set) {
        cudaFuncSetAttribute(qkv_gemm_kernel,
                             cudaFuncAttributeMaxDynamicSharedMemorySize, GM_SMEM);
        cudaFuncSetAttribute(out_gemm_kernel,
                             cudaFuncAttributeMaxDynamicSharedMemorySize, GM_SMEM);
        cudaFuncSetAttribute(flash_fp16_kernel,
                             cudaFuncAttributeMaxDynamicSharedMemorySize, FL_SMEM);
        smem_set = 1;
    }

    convert_kernel<<<dim3(2048, 1, 7), 256>>>(query, key, value, Wq, Wk, Wv, Wo);

    qkv_gemm_kernel<<<dim3(D_ / 128, M_ / 128, 3), 128, GM_SMEM>>>(bq, bk, bv);

    flash_fp16_kernel<<<dim3(S_ / 128, B_ * H_), 256, FL_SMEM>>>();

    out_gemm_kernel<<<dim3(D_ / 128, M_ / 128), 128, GM_SMEM>>>(bo, (float*)d_out);
}